// round 1
// baseline (speedup 1.0000x reference)
#include <cuda_runtime.h>

// HairBundle SDE drift + constant diffusion.
// x: [B,5] fp32 row-major. Outputs: drift [B,5] then diffusion [B,5] in d_out.
// Memory-bound: 160MB read + 320MB write ~= 480MB -> ~60-75us floor on GB300.

// --- model constants folded ---
// LAM=1, LAM_A=10, K_GS=0.75, K_SP=0.6, K_ES=0.45, D_GATE=0.5, DELTA=0.25
// F_MAX=0.35, S_CA=0.9, C_M=1.2, K_M=0.8, C_GS=0.7, K_GSR=0.5, C_T=0.3, K_T=0.4
// HB_NOISE=0.05, A_NOISE=0.02, F_AMP=0.5, F_OMEGA=2*pi, F_PHASE=0

__device__ __forceinline__ void hb_row(float x_hb, float x_a, float p_m,
                                       float p_gs, float p_t, float force,
                                       float* __restrict__ o) {
    float z    = 4.0f * (x_hb - x_a);                 // (x_hb - x_a)/DELTA
    float p_o  = 1.0f / (1.0f + __expf(-z));          // sigmoid
    float f_gs = 0.75f * (x_hb - x_a - 0.5f * p_o);
    o[0] = -f_gs - 0.6f * x_hb + force;                       // /LAM=1
    o[1] = 0.1f * (f_gs - 0.45f * x_a - 0.35f * (1.0f - 0.9f * p_m));
    o[2] = 1.2f * p_o * (1.0f - p_m)  - 0.8f * p_m;
    o[3] = 0.7f * p_o * (1.0f - p_gs) - 0.5f * p_gs;
    o[4] = 0.3f * p_o * (1.0f - p_t)  - 0.4f * p_t;
}

// Each thread processes 4 rows = 20 floats = 5 x float4 (16B-aligned since
// row-group byte offset is 80B and buffers are 256B-aligned).
__global__ __launch_bounds__(256)
void hb_quad_kernel(const float* __restrict__ t,
                    const float* __restrict__ x,
                    float* __restrict__ drift,
                    float* __restrict__ diffu,
                    int nquads) {
    int i = blockIdx.x * blockDim.x + threadIdx.x;
    if (i >= nquads) return;

    float force = 0.5f * __sinf(6.283185307179586f * t[0]);

    const float4* __restrict__ xin = reinterpret_cast<const float4*>(x) + (size_t)i * 5;
    float4 a = xin[0], b = xin[1], c = xin[2], d = xin[3], e = xin[4];

    float out[20];
    // row 0: a.x a.y a.z a.w b.x
    hb_row(a.x, a.y, a.z, a.w, b.x, force, out + 0);
    // row 1: b.y b.z b.w c.x c.y
    hb_row(b.y, b.z, b.w, c.x, c.y, force, out + 5);
    // row 2: c.z c.w d.x d.y d.z
    hb_row(c.z, c.w, d.x, d.y, d.z, force, out + 10);
    // row 3: d.w e.x e.y e.z e.w
    hb_row(d.w, e.x, e.y, e.z, e.w, force, out + 15);

    float4* __restrict__ dout = reinterpret_cast<float4*>(drift) + (size_t)i * 5;
    dout[0] = make_float4(out[0],  out[1],  out[2],  out[3]);
    dout[1] = make_float4(out[4],  out[5],  out[6],  out[7]);
    dout[2] = make_float4(out[8],  out[9],  out[10], out[11]);
    dout[3] = make_float4(out[12], out[13], out[14], out[15]);
    dout[4] = make_float4(out[16], out[17], out[18], out[19]);

    // diffusion: tiled [0.05, 0.02, 0, 0, 0] over 20 consecutive floats
    float4* __restrict__ gout = reinterpret_cast<float4*>(diffu) + (size_t)i * 5;
    gout[0] = make_float4(0.05f, 0.02f, 0.0f,  0.0f);
    gout[1] = make_float4(0.0f,  0.05f, 0.02f, 0.0f);
    gout[2] = make_float4(0.0f,  0.0f,  0.05f, 0.02f);
    gout[3] = make_float4(0.0f,  0.0f,  0.0f,  0.05f);
    gout[4] = make_float4(0.02f, 0.0f,  0.0f,  0.0f);
}

// Scalar tail for B % 4 != 0 (not hit for B=8M, kept for safety).
__global__ void hb_tail_kernel(const float* __restrict__ t,
                               const float* __restrict__ x,
                               float* __restrict__ drift,
                               float* __restrict__ diffu,
                               int row0, int nrows) {
    int r = row0 + blockIdx.x * blockDim.x + threadIdx.x;
    if (r >= row0 + nrows) return;
    float force = 0.5f * __sinf(6.283185307179586f * t[0]);
    const float* xr = x + (size_t)r * 5;
    float o[5];
    hb_row(xr[0], xr[1], xr[2], xr[3], xr[4], force, o);
    float* dr = drift + (size_t)r * 5;
    float* gr = diffu + (size_t)r * 5;
    dr[0] = o[0]; dr[1] = o[1]; dr[2] = o[2]; dr[3] = o[3]; dr[4] = o[4];
    gr[0] = 0.05f; gr[1] = 0.02f; gr[2] = 0.0f; gr[3] = 0.0f; gr[4] = 0.0f;
}

extern "C" void kernel_launch(void* const* d_in, const int* in_sizes, int n_in,
                              void* d_out, int out_size) {
    const float* t = (const float*)d_in[0];   // [1]
    const float* x = (const float*)d_in[1];   // [B*5]
    float* out   = (float*)d_out;
    int B        = in_sizes[1] / 5;
    float* drift = out;                        // first half
    float* diffu = out + (size_t)out_size / 2; // second half

    int nquads = B / 4;
    int rem    = B - nquads * 4;

    const int TPB = 256;
    if (nquads > 0) {
        int blocks = (nquads + TPB - 1) / TPB;
        hb_quad_kernel<<<blocks, TPB>>>(t, x, drift, diffu, nquads);
    }
    if (rem > 0) {
        hb_tail_kernel<<<1, 32>>>(t, x, drift, diffu, nquads * 4, rem);
    }
}